// round 12
// baseline (speedup 1.0000x reference)
#include <cuda_runtime.h>
#include <cuda_bf16.h>
#include <cuda_fp16.h>
#include <cstdint>

// Problem constants (fixed by the reference)
#define MAXN 50000
#define MAXE 800000
#define IN_CH 128
#define HID 32
#define HEADS 8
#define F1 (HEADS*HID)   // 256
#define OUT_CH 64
#define NEG_SLOPE 0.2f
#define MAXT (MAXE + MAXN)   // edges incl. self loops

// ---------------- scratch (static device globals; no allocs allowed) --------
__device__ __half2 g_xs1h[(size_t)MAXN * (F1 / 2)];     // layer1 feats (fp16)
__device__ __half2 g_hh[(size_t)MAXN * (F1 / 2)];       // layer1 out (fp16)
__device__ __half2 g_xs2h[(size_t)MAXN * (OUT_CH / 2)]; // layer2 feats (fp16)
__device__ float   g_asrc1[MAXN * HEADS];
__device__ float   g_adst1[MAXN * HEADS];
__device__ float   g_asrc2[MAXN];
__device__ float   g_adst2[MAXN];
// CSR build scratch
__device__ int g_count[MAXN];
__device__ int g_psum[MAXN];
__device__ int g_bsum[256];
__device__ int g_rowstart[MAXN + 1];
__device__ int g_cursor[MAXN];
__device__ int g_csr_src[MAXT];

__device__ __forceinline__ float lrelu(float x) {
    return x > 0.f ? x : NEG_SLOPE * x;
}

// ---------------- CSR build --------------------------------------------------
__global__ void hist_kernel(const int* __restrict__ dst, int E, int n) {
    int i = blockIdx.x * blockDim.x + threadIdx.x;
    if (i >= E + n) return;
    int d = (i < E) ? dst[i] : (i - E);   // self loops appended
    atomicAdd(&g_count[d], 1);
}
__global__ void scan_blk_kernel(int n) {
    __shared__ int sh[256];
    int t = threadIdx.x;
    int i = blockIdx.x * 256 + t;
    int v = (i < n) ? g_count[i] : 0;
    sh[t] = v;
    __syncthreads();
    #pragma unroll
    for (int off = 1; off < 256; off <<= 1) {
        int x = (t >= off) ? sh[t - off] : 0;
        __syncthreads();
        sh[t] += x;
        __syncthreads();
    }
    if (i < n) g_psum[i] = sh[t] - v;     // exclusive
    if (t == 255) g_bsum[blockIdx.x] = sh[255];
}
// rows_kernel folds the top-level scan in: each block reduces bsum[0..bid-1].
__global__ void rows_kernel(int E, int n) {
    __shared__ int s_off;
    int t = threadIdx.x;
    if (t < 32) {
        int acc = 0;
        for (int i = t; i < blockIdx.x; i += 32) acc += g_bsum[i];
        #pragma unroll
        for (int o = 16; o; o >>= 1) acc += __shfl_down_sync(0xffffffffu, acc, o);
        if (t == 0) s_off = acc;
    }
    __syncthreads();
    int i = blockIdx.x * 256 + t;
    if (i < n) {
        int r = g_psum[i] + s_off;
        g_rowstart[i] = r;
        g_cursor[i] = r;
    }
    if (i == 0) g_rowstart[n] = E + n;
}
__global__ void scatter_kernel(const int* __restrict__ src,
                               const int* __restrict__ dst, int E, int n) {
    int i = blockIdx.x * blockDim.x + threadIdx.x;
    if (i >= E + n) return;
    int s, d;
    if (i < E) { s = src[i]; d = dst[i]; }
    else       { s = d = i - E; }
    int pos = atomicAdd(&g_cursor[d], 1);
    g_csr_src[pos] = s;
}

// ---------------- fp16 tensor-core GEMM --------------------------------------
__device__ __forceinline__ void mma_16x8x16(float4& d, const uint32_t* a,
                                            uint32_t b0, uint32_t b1) {
    asm volatile(
        "mma.sync.aligned.m16n8k16.row.col.f32.f16.f16.f32 "
        "{%0,%1,%2,%3}, {%4,%5,%6,%7}, {%8,%9}, {%0,%1,%2,%3};"
        : "+f"(d.x), "+f"(d.y), "+f"(d.z), "+f"(d.w)
        : "r"(a[0]), "r"(a[1]), "r"(a[2]), "r"(a[3]), "r"(b0), "r"(b1));
}

template<int BM, int BN, int BK, int WM, int WN, int MT, int NT, bool A_HALF>
__global__ void hgemm_tc(const void* __restrict__ Av,
                         const float* __restrict__ B,
                         __half* __restrict__ C, int M, int N, int K) {
    constexpr int THREADS = WM * WN * 32;
    __shared__ __align__(16) __half As[BM][BK + 8];
    __shared__ __align__(16) __half Bs[BK][BN + 8];
    const int tid = threadIdx.x;
    const int lane = tid & 31;
    const int wid = tid >> 5;
    const int warp_m = wid / WN;
    const int warp_n = wid % WN;
    const int rowBase = blockIdx.y * BM;
    const int colBase = blockIdx.x * BN;

    float4 acc[MT][NT] = {};

    for (int kb = 0; kb < K; kb += BK) {
        if (A_HALF) {
            const __half* A = (const __half*)Av;
            constexpr int ITERS = (BM * BK) / (8 * THREADS);
            #pragma unroll
            for (int i = 0; i < ITERS; i++) {
                int f = tid + i * THREADS;
                int r = f / (BK / 8), c8 = (f % (BK / 8)) * 8;
                int gr = rowBase + r;
                uint4 v = (gr < M) ? *(const uint4*)&A[(size_t)gr * K + kb + c8]
                                   : make_uint4(0u, 0u, 0u, 0u);
                *(uint4*)&As[r][c8] = v;
            }
        } else {
            const float* A = (const float*)Av;
            constexpr int ITERS = (BM * BK) / (4 * THREADS);
            #pragma unroll
            for (int i = 0; i < ITERS; i++) {
                int f = tid + i * THREADS;
                int r = f / (BK / 4), c4 = (f % (BK / 4)) * 4;
                int gr = rowBase + r;
                float4 v = (gr < M) ? *(const float4*)&A[(size_t)gr * K + kb + c4]
                                    : make_float4(0.f, 0.f, 0.f, 0.f);
                *(__half2*)&As[r][c4]     = __float22half2_rn(make_float2(v.x, v.y));
                *(__half2*)&As[r][c4 + 2] = __float22half2_rn(make_float2(v.z, v.w));
            }
        }
        {
            constexpr int ITERS = (BK * BN) / (4 * THREADS);
            #pragma unroll
            for (int i = 0; i < ITERS; i++) {
                int f = tid + i * THREADS;
                int r = f / (BN / 4), c4 = (f % (BN / 4)) * 4;
                float4 v = *(const float4*)&B[(size_t)(kb + r) * N + colBase + c4];
                *(__half2*)&Bs[r][c4]     = __float22half2_rn(make_float2(v.x, v.y));
                *(__half2*)&Bs[r][c4 + 2] = __float22half2_rn(make_float2(v.z, v.w));
            }
        }
        __syncthreads();
        #pragma unroll
        for (int ks = 0; ks < BK / 16; ks++) {
            uint32_t af[MT][4], bf[NT][2];
            #pragma unroll
            for (int ma = 0; ma < MT; ma++) {
                int row = warp_m * (MT * 16) + ma * 16 + (lane & 15);
                int col = ks * 16 + (lane >> 4) * 8;
                uint32_t addr = (uint32_t)__cvta_generic_to_shared(&As[row][col]);
                asm volatile(
                    "ldmatrix.sync.aligned.m8n8.x4.shared.b16 {%0,%1,%2,%3}, [%4];"
                    : "=r"(af[ma][0]), "=r"(af[ma][1]),
                      "=r"(af[ma][2]), "=r"(af[ma][3]) : "r"(addr));
            }
            #pragma unroll
            for (int na = 0; na < NT; na++) {
                int krow = ks * 16 + (lane & 15);
                int col = warp_n * (NT * 8) + na * 8;
                uint32_t addr = (uint32_t)__cvta_generic_to_shared(&Bs[krow][col]);
                asm volatile(
                    "ldmatrix.sync.aligned.m8n8.x2.trans.shared.b16 {%0,%1}, [%2];"
                    : "=r"(bf[na][0]), "=r"(bf[na][1]) : "r"(addr));
            }
            #pragma unroll
            for (int ma = 0; ma < MT; ma++)
                #pragma unroll
                for (int na = 0; na < NT; na++)
                    mma_16x8x16(acc[ma][na], af[ma], bf[na][0], bf[na][1]);
        }
        __syncthreads();
    }

    const int r_in = lane >> 2;
    const int c_in = (lane & 3) * 2;
    #pragma unroll
    for (int ma = 0; ma < MT; ma++) {
        int r0 = rowBase + warp_m * (MT * 16) + ma * 16 + r_in;
        #pragma unroll
        for (int na = 0; na < NT; na++) {
            int gc = colBase + warp_n * (NT * 8) + na * 8 + c_in;
            if (r0 < M)
                *(__half2*)&C[(size_t)r0 * N + gc] =
                    __float22half2_rn(make_float2(acc[ma][na].x, acc[ma][na].y));
            if (r0 + 8 < M)
                *(__half2*)&C[(size_t)(r0 + 8) * N + gc] =
                    __float22half2_rn(make_float2(acc[ma][na].z, acc[ma][na].w));
        }
    }
}

// ---------------- per-node attention dots -----------------------------------
__global__ void att_dot1_kernel(const float* __restrict__ att_src,
                                const float* __restrict__ att_dst, int n) {
    int idx = blockIdx.x * blockDim.x + threadIdx.x;
    if (idx >= n * HEADS) return;
    int node = idx >> 3, h = idx & 7;
    const __half2* xr = g_xs1h + (size_t)node * (F1 / 2) + h * (HID / 2);
    const float* as = att_src + h * HID;
    const float* ad = att_dst + h * HID;
    float ss = 0.f, sd = 0.f;
    #pragma unroll
    for (int c = 0; c < HID / 2; c++) {
        float2 v = __half22float2(xr[c]);
        ss += v.x * as[2 * c] + v.y * as[2 * c + 1];
        sd += v.x * ad[2 * c] + v.y * ad[2 * c + 1];
    }
    g_asrc1[idx] = ss;
    g_adst1[idx] = sd;
}
__global__ void att_dot2_kernel(const float* __restrict__ att_src,
                                const float* __restrict__ att_dst, int n) {
    int node = blockIdx.x * blockDim.x + threadIdx.x;
    if (node >= n) return;
    const __half2* xr = g_xs2h + (size_t)node * (OUT_CH / 2);
    float ss = 0.f, sd = 0.f;
    #pragma unroll
    for (int c = 0; c < OUT_CH / 2; c++) {
        float2 v = __half22float2(xr[c]);
        ss += v.x * att_src[2 * c] + v.y * att_src[2 * c + 1];
        sd += v.x * att_dst[2 * c] + v.y * att_dst[2 * c + 1];
    }
    g_asrc2[node] = ss;
    g_adst2[node] = sd;
}

// ---------------- CSR aggregation ---------------------------------------------
// TWO warps per dst node; each owns 4 heads / 128 channels. Per-head softmax
// denominators make the split communication-free. Per-edge per-warp gather is
// one LDG.64 (256 B/warp); warp count doubles -> 2x outstanding loads.
__device__ __forceinline__ void agg1_edge(int s, int half, float adst,
                                          int lane, int hsel,
                                          float& den, float4& acc) {
    float as = (lane < 4) ? g_asrc1[s * HEADS + half * 4 + lane] : 0.f;
    const uint2* xr = (const uint2*)(g_xs1h + (size_t)s * (F1 / 2) + half * 64);
    uint2 u = xr[lane];
    float ex = (lane < 4) ? __expf(lrelu(as + adst)) : 0.f;
    den += ex;
    float w = __shfl_sync(0xffffffffu, ex, hsel);
    float2 f0 = __half22float2(*(__half2*)&u.x);
    float2 f1 = __half22float2(*(__half2*)&u.y);
    acc.x += w * f0.x; acc.y += w * f0.y;
    acc.z += w * f1.x; acc.w += w * f1.y;
}

__global__ void agg1_csr_kernel(const float* __restrict__ bias, int n) {
    int gwarp = (blockIdx.x * blockDim.x + threadIdx.x) >> 5;
    int lane = threadIdx.x & 31;
    if (gwarp >= 2 * n) return;
    const int node = gwarp >> 1;
    const int half = gwarp & 1;
    const int start = g_rowstart[node];
    const int end   = g_rowstart[node + 1];
    const float adst = (lane < 4) ? g_adst1[node * HEADS + half * 4 + lane] : 0.f;
    const int hsel = lane >> 3;          // which of this half's 4 heads

    float4 acc = {0.f, 0.f, 0.f, 0.f};
    float den = 0.f;                     // lane h (<4) holds den for head h

    for (int base = start; base < end; base += 32) {
        int m = end - base; if (m > 32) m = 32;
        int idx = (base + lane < end) ? g_csr_src[base + lane] : 0;
        int t = 0;
        for (; t + 3 < m; t += 4) {
            int s0 = __shfl_sync(0xffffffffu, idx, t);
            int s1 = __shfl_sync(0xffffffffu, idx, t + 1);
            int s2 = __shfl_sync(0xffffffffu, idx, t + 2);
            int s3 = __shfl_sync(0xffffffffu, idx, t + 3);
            agg1_edge(s0, half, adst, lane, hsel, den, acc);
            agg1_edge(s1, half, adst, lane, hsel, den, acc);
            agg1_edge(s2, half, adst, lane, hsel, den, acc);
            agg1_edge(s3, half, adst, lane, hsel, den, acc);
        }
        for (; t < m; t++) {
            int s0 = __shfl_sync(0xffffffffu, idx, t);
            agg1_edge(s0, half, adst, lane, hsel, den, acc);
        }
    }
    float denh = __shfl_sync(0xffffffffu, den, hsel);
    float4 b = *(const float4*)&bias[half * 128 + lane * 4];
    float4 o;
    o.x = acc.x / denh + b.x; o.y = acc.y / denh + b.y;
    o.z = acc.z / denh + b.z; o.w = acc.w / denh + b.w;
    o.x = o.x > 0.f ? o.x : expm1f(o.x);
    o.y = o.y > 0.f ? o.y : expm1f(o.y);
    o.z = o.z > 0.f ? o.z : expm1f(o.z);
    o.w = o.w > 0.f ? o.w : expm1f(o.w);
    uint2 p;
    *(__half2*)&p.x = __float22half2_rn(make_float2(o.x, o.y));
    *(__half2*)&p.y = __float22half2_rn(make_float2(o.z, o.w));
    ((uint2*)(g_hh + (size_t)node * (F1 / 2) + half * 64))[lane] = p;
}

__device__ __forceinline__ void agg2_edge(int s, float adst, int lane,
                                          float& den, float2& acc) {
    float as = g_asrc2[s];
    float2 v = __half22float2(g_xs2h[(size_t)s * (OUT_CH / 2) + lane]);
    float ex = __expf(lrelu(as + adst));
    den += ex;
    acc.x += ex * v.x;
    acc.y += ex * v.y;
}

__global__ void agg2_csr_kernel(float* __restrict__ out,
                                const float* __restrict__ bias, int n) {
    int warp = (blockIdx.x * blockDim.x + threadIdx.x) >> 5;
    int lane = threadIdx.x & 31;
    if (warp >= n) return;
    const int node = warp;
    const int start = g_rowstart[node];
    const int end   = g_rowstart[node + 1];
    const float adst = g_adst2[node];

    float2 acc = {0.f, 0.f};
    float den = 0.f;
    for (int base = start; base < end; base += 32) {
        int m = end - base; if (m > 32) m = 32;
        int idx = (base + lane < end) ? g_csr_src[base + lane] : 0;
        int t = 0;
        for (; t + 7 < m; t += 8) {
            #pragma unroll
            for (int q = 0; q < 8; q++) {
                int s0 = __shfl_sync(0xffffffffu, idx, t + q);
                agg2_edge(s0, adst, lane, den, acc);
            }
        }
        for (; t < m; t++) {
            int s0 = __shfl_sync(0xffffffffu, idx, t);
            agg2_edge(s0, adst, lane, den, acc);
        }
    }
    float2 o;
    o.x = acc.x / den + bias[lane * 2];
    o.y = acc.y / den + bias[lane * 2 + 1];
    ((float2*)(out + (size_t)node * OUT_CH))[lane] = o;
}

// ---------------- launch -----------------------------------------------------
extern "C" void kernel_launch(void* const* d_in, const int* in_sizes, int n_in,
                              void* d_out, int out_size) {
    const float* x        = (const float*)d_in[0];
    const int*   eidx     = (const int*)d_in[1];     // int32 [2, E]
    const float* W1       = (const float*)d_in[2];
    const float* att_src1 = (const float*)d_in[3];
    const float* att_dst1 = (const float*)d_in[4];
    const float* bias1    = (const float*)d_in[5];
    const float* W2       = (const float*)d_in[6];
    const float* att_src2 = (const float*)d_in[7];
    const float* att_dst2 = (const float*)d_in[8];
    const float* bias2    = (const float*)d_in[9];
    float* out = (float*)d_out;

    // GB300 ATS trap: __device__ symbols as host-side kernel args resolve to
    // the HOST shadow address (silently readable via NVLink-C2C ATS!).
    // Resolve the real device addresses explicitly.
    static __half* p_xs1h = nullptr;
    static __half* p_hh   = nullptr;
    static __half* p_xs2h = nullptr;
    static int*    p_count = nullptr;
    static cudaStream_t s1 = nullptr;
    static cudaEvent_t  e_fork = nullptr, e_join = nullptr;
    if (!p_xs1h) {
        void* p;
        cudaGetSymbolAddress(&p, g_xs1h);  p_xs1h = (__half*)p;
        cudaGetSymbolAddress(&p, g_hh);    p_hh   = (__half*)p;
        cudaGetSymbolAddress(&p, g_xs2h);  p_xs2h = (__half*)p;
        cudaGetSymbolAddress(&p, g_count); p_count = (int*)p;
        cudaStreamCreateWithFlags(&s1, cudaStreamNonBlocking);
        cudaEventCreateWithFlags(&e_fork, cudaEventDisableTiming);
        cudaEventCreateWithFlags(&e_join, cudaEventDisableTiming);
    }

    const int n = in_sizes[0] / IN_CH;     // 50000
    const int E = in_sizes[1] / 2;         // 800000
    const int* src = eidx;
    const int* dst = eidx + E;

    const int T = 256;
    const int nb = (n + 255) / 256;        // scan blocks (196)

    // ---- fork: CSR build on side stream, overlapped with GEMM1/att_dot1 ----
    cudaEventRecord(e_fork, (cudaStream_t)0);
    cudaStreamWaitEvent(s1, e_fork, 0);
    cudaMemsetAsync(p_count, 0, n * sizeof(int), s1);
    hist_kernel<<<(E + n + T - 1) / T, T, 0, s1>>>(dst, E, n);
    scan_blk_kernel<<<nb, 256, 0, s1>>>(n);
    rows_kernel<<<nb, 256, 0, s1>>>(E, n);
    scatter_kernel<<<(E + n + T - 1) / T, T, 0, s1>>>(src, dst, E, n);
    cudaEventRecord(e_join, s1);

    // ---- layer 1 (fp16 TC GEMM) on main stream ----
    {
        dim3 grid(F1 / 128, (n + 127) / 128);
        hgemm_tc<128, 128, 32, 2, 4, 4, 4, false><<<grid, 256>>>(x, W1, p_xs1h, n, F1, IN_CH);
    }
    att_dot1_kernel<<<(n * HEADS + T - 1) / T, T>>>(att_src1, att_dst1, n);

    // ---- join: aggregation needs both the CSR and the attention scores ----
    cudaStreamWaitEvent((cudaStream_t)0, e_join, 0);
    agg1_csr_kernel<<<(2 * n * 32 + T - 1) / T, T>>>(bias1, n);

    // ---- layer 2 (fp16 TC GEMM) ----
    {
        dim3 grid(OUT_CH / 64, (n + 127) / 128);
        hgemm_tc<128, 64, 32, 4, 2, 2, 4, true><<<grid, 256>>>(p_hh, W2, p_xs2h, n, OUT_CH, F1);
    }
    att_dot2_kernel<<<(n + T - 1) / T, T>>>(att_src2, att_dst2, n);
    agg2_csr_kernel<<<(n * 32 + T - 1) / T, T>>>(out, bias2, n);
}

// round 13
// speedup vs baseline: 1.1770x; 1.1770x over previous
#include <cuda_runtime.h>
#include <cuda_bf16.h>
#include <cuda_fp16.h>
#include <cstdint>

// Problem constants (fixed by the reference)
#define MAXN 50000
#define MAXE 800000
#define IN_CH 128
#define HID 32
#define HEADS 8
#define F1 (HEADS*HID)   // 256
#define OUT_CH 64
#define NEG_SLOPE 0.2f
#define MAXT (MAXE + MAXN)   // edges incl. self loops

// ---------------- scratch (static device globals; no allocs allowed) --------
__device__ __half2 g_xs1h[(size_t)MAXN * (F1 / 2)];     // layer1 feats (fp16)
__device__ __half2 g_hh[(size_t)MAXN * (F1 / 2)];       // layer1 out (fp16)
__device__ __half2 g_xs2h[(size_t)MAXN * (OUT_CH / 2)]; // layer2 feats (fp16)
__device__ float   g_asrc1[MAXN * HEADS];
__device__ float   g_adst1[MAXN * HEADS];
__device__ float   g_asrc2[MAXN];
__device__ float   g_adst2[MAXN];
// CSR build scratch
__device__ int g_count[MAXN];
__device__ int g_psum[MAXN];
__device__ int g_bsum[256];
__device__ int g_rowstart[MAXN + 1];
__device__ int g_cursor[MAXN];
__device__ int g_csr_src[MAXT];

__device__ __forceinline__ float lrelu(float x) {
    return x > 0.f ? x : NEG_SLOPE * x;
}

// ---------------- CSR build --------------------------------------------------
__global__ void hist_kernel(const int* __restrict__ dst, int E, int n) {
    int i = blockIdx.x * blockDim.x + threadIdx.x;
    if (i >= E + n) return;
    int d = (i < E) ? dst[i] : (i - E);   // self loops appended
    atomicAdd(&g_count[d], 1);
}
__global__ void scan_blk_kernel(int n) {
    __shared__ int sh[256];
    int t = threadIdx.x;
    int i = blockIdx.x * 256 + t;
    int v = (i < n) ? g_count[i] : 0;
    sh[t] = v;
    __syncthreads();
    #pragma unroll
    for (int off = 1; off < 256; off <<= 1) {
        int x = (t >= off) ? sh[t - off] : 0;
        __syncthreads();
        sh[t] += x;
        __syncthreads();
    }
    if (i < n) g_psum[i] = sh[t] - v;     // exclusive
    if (t == 255) g_bsum[blockIdx.x] = sh[255];
}
// rows_kernel folds the top-level scan in: each block reduces bsum[0..bid-1].
__global__ void rows_kernel(int E, int n) {
    __shared__ int s_off;
    int t = threadIdx.x;
    if (t < 32) {
        int acc = 0;
        for (int i = t; i < blockIdx.x; i += 32) acc += g_bsum[i];
        #pragma unroll
        for (int o = 16; o; o >>= 1) acc += __shfl_down_sync(0xffffffffu, acc, o);
        if (t == 0) s_off = acc;
    }
    __syncthreads();
    int i = blockIdx.x * 256 + t;
    if (i < n) {
        int r = g_psum[i] + s_off;
        g_rowstart[i] = r;
        g_cursor[i] = r;
    }
    if (i == 0) g_rowstart[n] = E + n;
}
__global__ void scatter_kernel(const int* __restrict__ src,
                               const int* __restrict__ dst, int E, int n) {
    int i = blockIdx.x * blockDim.x + threadIdx.x;
    if (i >= E + n) return;
    int s, d;
    if (i < E) { s = src[i]; d = dst[i]; }
    else       { s = d = i - E; }
    int pos = atomicAdd(&g_cursor[d], 1);
    g_csr_src[pos] = s;
}

// ---------------- fp16 tensor-core GEMM --------------------------------------
__device__ __forceinline__ void mma_16x8x16(float4& d, const uint32_t* a,
                                            uint32_t b0, uint32_t b1) {
    asm volatile(
        "mma.sync.aligned.m16n8k16.row.col.f32.f16.f16.f32 "
        "{%0,%1,%2,%3}, {%4,%5,%6,%7}, {%8,%9}, {%0,%1,%2,%3};"
        : "+f"(d.x), "+f"(d.y), "+f"(d.z), "+f"(d.w)
        : "r"(a[0]), "r"(a[1]), "r"(a[2]), "r"(a[3]), "r"(b0), "r"(b1));
}

template<int BM, int BN, int BK, int WM, int WN, int MT, int NT, bool A_HALF>
__global__ void hgemm_tc(const void* __restrict__ Av,
                         const float* __restrict__ B,
                         __half* __restrict__ C, int M, int N, int K) {
    constexpr int THREADS = WM * WN * 32;
    __shared__ __align__(16) __half As[BM][BK + 8];
    __shared__ __align__(16) __half Bs[BK][BN + 8];
    const int tid = threadIdx.x;
    const int lane = tid & 31;
    const int wid = tid >> 5;
    const int warp_m = wid / WN;
    const int warp_n = wid % WN;
    const int rowBase = blockIdx.y * BM;
    const int colBase = blockIdx.x * BN;

    float4 acc[MT][NT] = {};

    for (int kb = 0; kb < K; kb += BK) {
        if (A_HALF) {
            const __half* A = (const __half*)Av;
            constexpr int ITERS = (BM * BK) / (8 * THREADS);
            #pragma unroll
            for (int i = 0; i < ITERS; i++) {
                int f = tid + i * THREADS;
                int r = f / (BK / 8), c8 = (f % (BK / 8)) * 8;
                int gr = rowBase + r;
                uint4 v = (gr < M) ? *(const uint4*)&A[(size_t)gr * K + kb + c8]
                                   : make_uint4(0u, 0u, 0u, 0u);
                *(uint4*)&As[r][c8] = v;
            }
        } else {
            const float* A = (const float*)Av;
            constexpr int ITERS = (BM * BK) / (4 * THREADS);
            #pragma unroll
            for (int i = 0; i < ITERS; i++) {
                int f = tid + i * THREADS;
                int r = f / (BK / 4), c4 = (f % (BK / 4)) * 4;
                int gr = rowBase + r;
                float4 v = (gr < M) ? *(const float4*)&A[(size_t)gr * K + kb + c4]
                                    : make_float4(0.f, 0.f, 0.f, 0.f);
                *(__half2*)&As[r][c4]     = __float22half2_rn(make_float2(v.x, v.y));
                *(__half2*)&As[r][c4 + 2] = __float22half2_rn(make_float2(v.z, v.w));
            }
        }
        {
            constexpr int ITERS = (BK * BN) / (4 * THREADS);
            #pragma unroll
            for (int i = 0; i < ITERS; i++) {
                int f = tid + i * THREADS;
                int r = f / (BN / 4), c4 = (f % (BN / 4)) * 4;
                float4 v = *(const float4*)&B[(size_t)(kb + r) * N + colBase + c4];
                *(__half2*)&Bs[r][c4]     = __float22half2_rn(make_float2(v.x, v.y));
                *(__half2*)&Bs[r][c4 + 2] = __float22half2_rn(make_float2(v.z, v.w));
            }
        }
        __syncthreads();
        #pragma unroll
        for (int ks = 0; ks < BK / 16; ks++) {
            uint32_t af[MT][4], bf[NT][2];
            #pragma unroll
            for (int ma = 0; ma < MT; ma++) {
                int row = warp_m * (MT * 16) + ma * 16 + (lane & 15);
                int col = ks * 16 + (lane >> 4) * 8;
                uint32_t addr = (uint32_t)__cvta_generic_to_shared(&As[row][col]);
                asm volatile(
                    "ldmatrix.sync.aligned.m8n8.x4.shared.b16 {%0,%1,%2,%3}, [%4];"
                    : "=r"(af[ma][0]), "=r"(af[ma][1]),
                      "=r"(af[ma][2]), "=r"(af[ma][3]) : "r"(addr));
            }
            #pragma unroll
            for (int na = 0; na < NT; na++) {
                int krow = ks * 16 + (lane & 15);
                int col = warp_n * (NT * 8) + na * 8;
                uint32_t addr = (uint32_t)__cvta_generic_to_shared(&Bs[krow][col]);
                asm volatile(
                    "ldmatrix.sync.aligned.m8n8.x2.trans.shared.b16 {%0,%1}, [%2];"
                    : "=r"(bf[na][0]), "=r"(bf[na][1]) : "r"(addr));
            }
            #pragma unroll
            for (int ma = 0; ma < MT; ma++)
                #pragma unroll
                for (int na = 0; na < NT; na++)
                    mma_16x8x16(acc[ma][na], af[ma], bf[na][0], bf[na][1]);
        }
        __syncthreads();
    }

    const int r_in = lane >> 2;
    const int c_in = (lane & 3) * 2;
    #pragma unroll
    for (int ma = 0; ma < MT; ma++) {
        int r0 = rowBase + warp_m * (MT * 16) + ma * 16 + r_in;
        #pragma unroll
        for (int na = 0; na < NT; na++) {
            int gc = colBase + warp_n * (NT * 8) + na * 8 + c_in;
            if (r0 < M)
                *(__half2*)&C[(size_t)r0 * N + gc] =
                    __float22half2_rn(make_float2(acc[ma][na].x, acc[ma][na].y));
            if (r0 + 8 < M)
                *(__half2*)&C[(size_t)(r0 + 8) * N + gc] =
                    __float22half2_rn(make_float2(acc[ma][na].z, acc[ma][na].w));
        }
    }
}

// ---------------- per-node attention dots -----------------------------------
__global__ void att_dot1_kernel(const float* __restrict__ att_src,
                                const float* __restrict__ att_dst, int n) {
    int idx = blockIdx.x * blockDim.x + threadIdx.x;
    if (idx >= n * HEADS) return;
    int node = idx >> 3, h = idx & 7;
    const __half2* xr = g_xs1h + (size_t)node * (F1 / 2) + h * (HID / 2);
    const float* as = att_src + h * HID;
    const float* ad = att_dst + h * HID;
    float ss = 0.f, sd = 0.f;
    #pragma unroll
    for (int c = 0; c < HID / 2; c++) {
        float2 v = __half22float2(xr[c]);
        ss += v.x * as[2 * c] + v.y * as[2 * c + 1];
        sd += v.x * ad[2 * c] + v.y * ad[2 * c + 1];
    }
    g_asrc1[idx] = ss;
    g_adst1[idx] = sd;
}
__global__ void att_dot2_kernel(const float* __restrict__ att_src,
                                const float* __restrict__ att_dst, int n) {
    int node = blockIdx.x * blockDim.x + threadIdx.x;
    if (node >= n) return;
    const __half2* xr = g_xs2h + (size_t)node * (OUT_CH / 2);
    float ss = 0.f, sd = 0.f;
    #pragma unroll
    for (int c = 0; c < OUT_CH / 2; c++) {
        float2 v = __half22float2(xr[c]);
        ss += v.x * att_src[2 * c] + v.y * att_src[2 * c + 1];
        sd += v.x * att_dst[2 * c] + v.y * att_dst[2 * c + 1];
    }
    g_asrc2[node] = ss;
    g_adst2[node] = sd;
}

// ---------------- CSR aggregation: one warp per dst node ----------------------
// Lane l owns channels [8l..8l+7]: ONE LDG.128 per edge per lane (512 B/warp,
// half the gather instructions of the 2x LDG.64 layout). Head sel = l>>2.
__device__ __forceinline__ void agg1_edge(int s, float adst, int lane, int hsel,
                                          float& den, float4& accA, float4& accB) {
    float as = (lane < HEADS) ? g_asrc1[s * HEADS + lane] : 0.f;
    uint4 u = ((const uint4*)(g_xs1h + (size_t)s * (F1 / 2)))[lane];
    float ex = (lane < HEADS) ? __expf(lrelu(as + adst)) : 0.f;
    den += ex;
    float w = __shfl_sync(0xffffffffu, ex, hsel);
    float2 f0 = __half22float2(*(__half2*)&u.x);
    float2 f1 = __half22float2(*(__half2*)&u.y);
    float2 f2 = __half22float2(*(__half2*)&u.z);
    float2 f3 = __half22float2(*(__half2*)&u.w);
    accA.x += w * f0.x; accA.y += w * f0.y;
    accA.z += w * f1.x; accA.w += w * f1.y;
    accB.x += w * f2.x; accB.y += w * f2.y;
    accB.z += w * f3.x; accB.w += w * f3.y;
}

__global__ void agg1_csr_kernel(const float* __restrict__ bias, int n) {
    int warp = (blockIdx.x * blockDim.x + threadIdx.x) >> 5;
    int lane = threadIdx.x & 31;
    if (warp >= n) return;
    const int node = warp;
    const int start = g_rowstart[node];
    const int end   = g_rowstart[node + 1];
    const float adst = (lane < HEADS) ? g_adst1[node * HEADS + lane] : 0.f;
    const int hsel = lane >> 2;         // head owning channels [8l..8l+7]

    float4 accA = {0.f, 0.f, 0.f, 0.f};
    float4 accB = {0.f, 0.f, 0.f, 0.f};
    float den = 0.f;                    // lane h (<8) holds den for head h

    for (int base = start; base < end; base += 32) {
        int m = end - base; if (m > 32) m = 32;
        int idx = (base + lane < end) ? g_csr_src[base + lane] : 0;
        int t = 0;
        for (; t + 3 < m; t += 4) {
            int s0 = __shfl_sync(0xffffffffu, idx, t);
            int s1 = __shfl_sync(0xffffffffu, idx, t + 1);
            int s2 = __shfl_sync(0xffffffffu, idx, t + 2);
            int s3 = __shfl_sync(0xffffffffu, idx, t + 3);
            agg1_edge(s0, adst, lane, hsel, den, accA, accB);
            agg1_edge(s1, adst, lane, hsel, den, accA, accB);
            agg1_edge(s2, adst, lane, hsel, den, accA, accB);
            agg1_edge(s3, adst, lane, hsel, den, accA, accB);
        }
        for (; t < m; t++) {
            int s0 = __shfl_sync(0xffffffffu, idx, t);
            agg1_edge(s0, adst, lane, hsel, den, accA, accB);
        }
    }
    float denh = __shfl_sync(0xffffffffu, den, hsel);
    float4 bA = *(const float4*)&bias[lane * 8];
    float4 bB = *(const float4*)&bias[lane * 8 + 4];
    float4 oA, oB;
    oA.x = accA.x / denh + bA.x; oA.y = accA.y / denh + bA.y;
    oA.z = accA.z / denh + bA.z; oA.w = accA.w / denh + bA.w;
    oB.x = accB.x / denh + bB.x; oB.y = accB.y / denh + bB.y;
    oB.z = accB.z / denh + bB.z; oB.w = accB.w / denh + bB.w;
    oA.x = oA.x > 0.f ? oA.x : expm1f(oA.x);
    oA.y = oA.y > 0.f ? oA.y : expm1f(oA.y);
    oA.z = oA.z > 0.f ? oA.z : expm1f(oA.z);
    oA.w = oA.w > 0.f ? oA.w : expm1f(oA.w);
    oB.x = oB.x > 0.f ? oB.x : expm1f(oB.x);
    oB.y = oB.y > 0.f ? oB.y : expm1f(oB.y);
    oB.z = oB.z > 0.f ? oB.z : expm1f(oB.z);
    oB.w = oB.w > 0.f ? oB.w : expm1f(oB.w);
    uint4 p;
    *(__half2*)&p.x = __float22half2_rn(make_float2(oA.x, oA.y));
    *(__half2*)&p.y = __float22half2_rn(make_float2(oA.z, oA.w));
    *(__half2*)&p.z = __float22half2_rn(make_float2(oB.x, oB.y));
    *(__half2*)&p.w = __float22half2_rn(make_float2(oB.z, oB.w));
    ((uint4*)(g_hh + (size_t)node * (F1 / 2)))[lane] = p;
}

// agg2: half-warps own alternating edges; lane sl<16 covers channels
// [4sl..4sl+3] via one LDG.64. Halves combined at the end with shfl_xor(16).
__global__ void agg2_csr_kernel(float* __restrict__ out,
                                const float* __restrict__ bias, int n) {
    int warp = (blockIdx.x * blockDim.x + threadIdx.x) >> 5;
    int lane = threadIdx.x & 31;
    if (warp >= n) return;
    const int node = warp;
    const int half = lane >> 4;
    const int sl = lane & 15;
    const int start = g_rowstart[node];
    const int end   = g_rowstart[node + 1];
    const float adst = g_adst2[node];

    float4 acc = {0.f, 0.f, 0.f, 0.f};
    float den = 0.f;
    for (int base = start; base < end; base += 32) {
        int m = end - base; if (m > 32) m = 32;
        int idx = (base + lane < end) ? g_csr_src[base + lane] : 0;
        int t = 0;
        for (; t + 1 < m; t += 2) {
            int s = __shfl_sync(0xffffffffu, idx, t + half);
            float as = g_asrc2[s];
            uint2 u = ((const uint2*)(g_xs2h + (size_t)s * (OUT_CH / 2)))[sl];
            float ex = __expf(lrelu(as + adst));
            den += ex;
            float2 f0 = __half22float2(*(__half2*)&u.x);
            float2 f1 = __half22float2(*(__half2*)&u.y);
            acc.x += ex * f0.x; acc.y += ex * f0.y;
            acc.z += ex * f1.x; acc.w += ex * f1.y;
        }
        if (t < m) {
            int s = __shfl_sync(0xffffffffu, idx, t);
            if (half == 0) {
                float as = g_asrc2[s];
                uint2 u = ((const uint2*)(g_xs2h + (size_t)s * (OUT_CH / 2)))[sl];
                float ex = __expf(lrelu(as + adst));
                den += ex;
                float2 f0 = __half22float2(*(__half2*)&u.x);
                float2 f1 = __half22float2(*(__half2*)&u.y);
                acc.x += ex * f0.x; acc.y += ex * f0.y;
                acc.z += ex * f1.x; acc.w += ex * f1.y;
            }
        }
    }
    // combine the two half-warps (same channels, disjoint edge subsets)
    den   += __shfl_xor_sync(0xffffffffu, den, 16);
    acc.x += __shfl_xor_sync(0xffffffffu, acc.x, 16);
    acc.y += __shfl_xor_sync(0xffffffffu, acc.y, 16);
    acc.z += __shfl_xor_sync(0xffffffffu, acc.z, 16);
    acc.w += __shfl_xor_sync(0xffffffffu, acc.w, 16);
    if (half == 0) {
        float4 b = *(const float4*)&bias[sl * 4];
        float4 o;
        o.x = acc.x / den + b.x; o.y = acc.y / den + b.y;
        o.z = acc.z / den + b.z; o.w = acc.w / den + b.w;
        ((float4*)(out + (size_t)node * OUT_CH))[sl] = o;
    }
}

// ---------------- launch -----------------------------------------------------
extern "C" void kernel_launch(void* const* d_in, const int* in_sizes, int n_in,
                              void* d_out, int out_size) {
    const float* x        = (const float*)d_in[0];
    const int*   eidx     = (const int*)d_in[1];     // int32 [2, E]
    const float* W1       = (const float*)d_in[2];
    const float* att_src1 = (const float*)d_in[3];
    const float* att_dst1 = (const float*)d_in[4];
    const float* bias1    = (const float*)d_in[5];
    const float* W2       = (const float*)d_in[6];
    const float* att_src2 = (const float*)d_in[7];
    const float* att_dst2 = (const float*)d_in[8];
    const float* bias2    = (const float*)d_in[9];
    float* out = (float*)d_out;

    // GB300 ATS trap: __device__ symbols as host-side kernel args resolve to
    // the HOST shadow address (silently readable via NVLink-C2C ATS!).
    // Resolve the real device addresses explicitly.
    static __half* p_xs1h = nullptr;
    static __half* p_hh   = nullptr;
    static __half* p_xs2h = nullptr;
    static int*    p_count = nullptr;
    static cudaStream_t s1 = nullptr;
    static cudaEvent_t  e_fork = nullptr, e_join = nullptr;
    if (!p_xs1h) {
        void* p;
        cudaGetSymbolAddress(&p, g_xs1h);  p_xs1h = (__half*)p;
        cudaGetSymbolAddress(&p, g_hh);    p_hh   = (__half*)p;
        cudaGetSymbolAddress(&p, g_xs2h);  p_xs2h = (__half*)p;
        cudaGetSymbolAddress(&p, g_count); p_count = (int*)p;
        cudaStreamCreateWithFlags(&s1, cudaStreamNonBlocking);
        cudaEventCreateWithFlags(&e_fork, cudaEventDisableTiming);
        cudaEventCreateWithFlags(&e_join, cudaEventDisableTiming);
    }

    const int n = in_sizes[0] / IN_CH;     // 50000
    const int E = in_sizes[1] / 2;         // 800000
    const int* src = eidx;
    const int* dst = eidx + E;

    const int T = 256;
    const int nb = (n + 255) / 256;        // scan blocks (196)

    // ---- fork: CSR build on side stream, overlapped with GEMM1/att_dot1 ----
    cudaEventRecord(e_fork, (cudaStream_t)0);
    cudaStreamWaitEvent(s1, e_fork, 0);
    cudaMemsetAsync(p_count, 0, n * sizeof(int), s1);
    hist_kernel<<<(E + n + T - 1) / T, T, 0, s1>>>(dst, E, n);
    scan_blk_kernel<<<nb, 256, 0, s1>>>(n);
    rows_kernel<<<nb, 256, 0, s1>>>(E, n);
    scatter_kernel<<<(E + n + T - 1) / T, T, 0, s1>>>(src, dst, E, n);
    cudaEventRecord(e_join, s1);

    // ---- layer 1 (fp16 TC GEMM) on main stream ----
    {
        dim3 grid(F1 / 128, (n + 127) / 128);
        hgemm_tc<128, 128, 32, 2, 4, 4, 4, false><<<grid, 256>>>(x, W1, p_xs1h, n, F1, IN_CH);
    }
    att_dot1_kernel<<<(n * HEADS + T - 1) / T, T>>>(att_src1, att_dst1, n);

    // ---- join: aggregation needs both the CSR and the attention scores ----
    cudaStreamWaitEvent((cudaStream_t)0, e_join, 0);
    agg1_csr_kernel<<<(n * 32 + T - 1) / T, T>>>(bias1, n);

    // ---- layer 2 (fp16 TC GEMM) ----
    {
        dim3 grid(OUT_CH / 64, (n + 127) / 128);
        hgemm_tc<128, 64, 32, 4, 2, 2, 4, true><<<grid, 256>>>(p_hh, W2, p_xs2h, n, OUT_CH, F1);
    }
    att_dot2_kernel<<<(n + T - 1) / T, T>>>(att_src2, att_dst2, n);
    agg2_csr_kernel<<<(n * 32 + T - 1) / T, T>>>(out, bias2, n);
}

// round 14
// speedup vs baseline: 1.1908x; 1.0117x over previous
#include <cuda_runtime.h>
#include <cuda_bf16.h>
#include <cuda_fp16.h>
#include <cstdint>

// Problem constants (fixed by the reference)
#define MAXN 50000
#define MAXE 800000
#define IN_CH 128
#define HID 32
#define HEADS 8
#define F1 (HEADS*HID)   // 256
#define OUT_CH 64
#define NEG_SLOPE 0.2f
#define MAXT (MAXE + MAXN)   // edges incl. self loops

// ---------------- scratch (static device globals; no allocs allowed) --------
__device__ __half2 g_xs1h[(size_t)MAXN * (F1 / 2)];     // layer1 feats (fp16)
__device__ __half2 g_hh[(size_t)MAXN * (F1 / 2)];       // layer1 out (fp16)
__device__ __half2 g_xs2h[(size_t)MAXN * (OUT_CH / 2)]; // layer2 feats (fp16)
__device__ float   g_asrc1[MAXN * HEADS];
__device__ float   g_adst1[MAXN * HEADS];
__device__ float   g_asrc2[MAXN];
__device__ float   g_adst2[MAXN];
// CSR build scratch
__device__ int g_count[MAXN];
__device__ int g_psum[MAXN];
__device__ int g_bsum[256];
__device__ int g_rowstart[MAXN + 1];
__device__ int g_cursor[MAXN];
__device__ int g_csr_src[MAXT];

__device__ __forceinline__ float lrelu(float x) {
    return x > 0.f ? x : NEG_SLOPE * x;
}

// ---------------- CSR build --------------------------------------------------
// 4 elements per thread (independent atomics pipeline; coalesced per pass).
__global__ void hist_kernel(const int* __restrict__ dst, int E, int n) {
    int base = blockIdx.x * blockDim.x * 4 + threadIdx.x;
    #pragma unroll
    for (int k = 0; k < 4; k++) {
        int i = base + k * blockDim.x;
        if (i < E + n) {
            int d = (i < E) ? dst[i] : (i - E);   // self loops appended
            atomicAdd(&g_count[d], 1);
        }
    }
}
__global__ void scan_blk_kernel(int n) {
    __shared__ int sh[256];
    int t = threadIdx.x;
    int i = blockIdx.x * 256 + t;
    int v = (i < n) ? g_count[i] : 0;
    sh[t] = v;
    __syncthreads();
    #pragma unroll
    for (int off = 1; off < 256; off <<= 1) {
        int x = (t >= off) ? sh[t - off] : 0;
        __syncthreads();
        sh[t] += x;
        __syncthreads();
    }
    if (i < n) g_psum[i] = sh[t] - v;     // exclusive
    if (t == 255) g_bsum[blockIdx.x] = sh[255];
}
// rows_kernel folds the top-level scan in: each block reduces bsum[0..bid-1].
__global__ void rows_kernel(int E, int n) {
    __shared__ int s_off;
    int t = threadIdx.x;
    if (t < 32) {
        int acc = 0;
        for (int i = t; i < blockIdx.x; i += 32) acc += g_bsum[i];
        #pragma unroll
        for (int o = 16; o; o >>= 1) acc += __shfl_down_sync(0xffffffffu, acc, o);
        if (t == 0) s_off = acc;
    }
    __syncthreads();
    int i = blockIdx.x * 256 + t;
    if (i < n) {
        int r = g_psum[i] + s_off;
        g_rowstart[i] = r;
        g_cursor[i] = r;
    }
    if (i == 0) g_rowstart[n] = E + n;
}
__global__ void scatter_kernel(const int* __restrict__ src,
                               const int* __restrict__ dst, int E, int n) {
    int base = blockIdx.x * blockDim.x * 4 + threadIdx.x;
    int s[4], d[4];
    bool ok[4];
    #pragma unroll
    for (int k = 0; k < 4; k++) {
        int i = base + k * blockDim.x;
        ok[k] = (i < E + n);
        if (ok[k]) {
            if (i < E) { s[k] = src[i]; d[k] = dst[i]; }
            else       { s[k] = d[k] = i - E; }
        }
    }
    int pos[4];
    #pragma unroll
    for (int k = 0; k < 4; k++)
        if (ok[k]) pos[k] = atomicAdd(&g_cursor[d[k]], 1);
    #pragma unroll
    for (int k = 0; k < 4; k++)
        if (ok[k]) g_csr_src[pos[k]] = s[k];
}

// ---------------- fp16 tensor-core GEMM --------------------------------------
__device__ __forceinline__ void mma_16x8x16(float4& d, const uint32_t* a,
                                            uint32_t b0, uint32_t b1) {
    asm volatile(
        "mma.sync.aligned.m16n8k16.row.col.f32.f16.f16.f32 "
        "{%0,%1,%2,%3}, {%4,%5,%6,%7}, {%8,%9}, {%0,%1,%2,%3};"
        : "+f"(d.x), "+f"(d.y), "+f"(d.z), "+f"(d.w)
        : "r"(a[0]), "r"(a[1]), "r"(a[2]), "r"(a[3]), "r"(b0), "r"(b1));
}

template<int BM, int BN, int BK, int WM, int WN, int MT, int NT, bool A_HALF>
__global__ void hgemm_tc(const void* __restrict__ Av,
                         const float* __restrict__ B,
                         __half* __restrict__ C, int M, int N, int K) {
    constexpr int THREADS = WM * WN * 32;
    __shared__ __align__(16) __half As[BM][BK + 8];
    __shared__ __align__(16) __half Bs[BK][BN + 8];
    const int tid = threadIdx.x;
    const int lane = tid & 31;
    const int wid = tid >> 5;
    const int warp_m = wid / WN;
    const int warp_n = wid % WN;
    const int rowBase = blockIdx.y * BM;
    const int colBase = blockIdx.x * BN;

    float4 acc[MT][NT] = {};

    for (int kb = 0; kb < K; kb += BK) {
        if (A_HALF) {
            const __half* A = (const __half*)Av;
            constexpr int ITERS = (BM * BK) / (8 * THREADS);
            #pragma unroll
            for (int i = 0; i < ITERS; i++) {
                int f = tid + i * THREADS;
                int r = f / (BK / 8), c8 = (f % (BK / 8)) * 8;
                int gr = rowBase + r;
                uint4 v = (gr < M) ? *(const uint4*)&A[(size_t)gr * K + kb + c8]
                                   : make_uint4(0u, 0u, 0u, 0u);
                *(uint4*)&As[r][c8] = v;
            }
        } else {
            const float* A = (const float*)Av;
            constexpr int ITERS = (BM * BK) / (4 * THREADS);
            #pragma unroll
            for (int i = 0; i < ITERS; i++) {
                int f = tid + i * THREADS;
                int r = f / (BK / 4), c4 = (f % (BK / 4)) * 4;
                int gr = rowBase + r;
                float4 v = (gr < M) ? *(const float4*)&A[(size_t)gr * K + kb + c4]
                                    : make_float4(0.f, 0.f, 0.f, 0.f);
                *(__half2*)&As[r][c4]     = __float22half2_rn(make_float2(v.x, v.y));
                *(__half2*)&As[r][c4 + 2] = __float22half2_rn(make_float2(v.z, v.w));
            }
        }
        {
            constexpr int ITERS = (BK * BN) / (4 * THREADS);
            #pragma unroll
            for (int i = 0; i < ITERS; i++) {
                int f = tid + i * THREADS;
                int r = f / (BN / 4), c4 = (f % (BN / 4)) * 4;
                float4 v = *(const float4*)&B[(size_t)(kb + r) * N + colBase + c4];
                *(__half2*)&Bs[r][c4]     = __float22half2_rn(make_float2(v.x, v.y));
                *(__half2*)&Bs[r][c4 + 2] = __float22half2_rn(make_float2(v.z, v.w));
            }
        }
        __syncthreads();
        #pragma unroll
        for (int ks = 0; ks < BK / 16; ks++) {
            uint32_t af[MT][4], bf[NT][2];
            #pragma unroll
            for (int ma = 0; ma < MT; ma++) {
                int row = warp_m * (MT * 16) + ma * 16 + (lane & 15);
                int col = ks * 16 + (lane >> 4) * 8;
                uint32_t addr = (uint32_t)__cvta_generic_to_shared(&As[row][col]);
                asm volatile(
                    "ldmatrix.sync.aligned.m8n8.x4.shared.b16 {%0,%1,%2,%3}, [%4];"
                    : "=r"(af[ma][0]), "=r"(af[ma][1]),
                      "=r"(af[ma][2]), "=r"(af[ma][3]) : "r"(addr));
            }
            #pragma unroll
            for (int na = 0; na < NT; na++) {
                int krow = ks * 16 + (lane & 15);
                int col = warp_n * (NT * 8) + na * 8;
                uint32_t addr = (uint32_t)__cvta_generic_to_shared(&Bs[krow][col]);
                asm volatile(
                    "ldmatrix.sync.aligned.m8n8.x2.trans.shared.b16 {%0,%1}, [%2];"
                    : "=r"(bf[na][0]), "=r"(bf[na][1]) : "r"(addr));
            }
            #pragma unroll
            for (int ma = 0; ma < MT; ma++)
                #pragma unroll
                for (int na = 0; na < NT; na++)
                    mma_16x8x16(acc[ma][na], af[ma], bf[na][0], bf[na][1]);
        }
        __syncthreads();
    }

    const int r_in = lane >> 2;
    const int c_in = (lane & 3) * 2;
    #pragma unroll
    for (int ma = 0; ma < MT; ma++) {
        int r0 = rowBase + warp_m * (MT * 16) + ma * 16 + r_in;
        #pragma unroll
        for (int na = 0; na < NT; na++) {
            int gc = colBase + warp_n * (NT * 8) + na * 8 + c_in;
            if (r0 < M)
                *(__half2*)&C[(size_t)r0 * N + gc] =
                    __float22half2_rn(make_float2(acc[ma][na].x, acc[ma][na].y));
            if (r0 + 8 < M)
                *(__half2*)&C[(size_t)(r0 + 8) * N + gc] =
                    __float22half2_rn(make_float2(acc[ma][na].z, acc[ma][na].w));
        }
    }
}

// ---------------- per-node attention dots -----------------------------------
__global__ void att_dot1_kernel(const float* __restrict__ att_src,
                                const float* __restrict__ att_dst, int n) {
    int idx = blockIdx.x * blockDim.x + threadIdx.x;
    if (idx >= n * HEADS) return;
    int node = idx >> 3, h = idx & 7;
    const __half2* xr = g_xs1h + (size_t)node * (F1 / 2) + h * (HID / 2);
    const float* as = att_src + h * HID;
    const float* ad = att_dst + h * HID;
    float ss = 0.f, sd = 0.f;
    #pragma unroll
    for (int c = 0; c < HID / 2; c++) {
        float2 v = __half22float2(xr[c]);
        ss += v.x * as[2 * c] + v.y * as[2 * c + 1];
        sd += v.x * ad[2 * c] + v.y * ad[2 * c + 1];
    }
    g_asrc1[idx] = ss;
    g_adst1[idx] = sd;
}
__global__ void att_dot2_kernel(const float* __restrict__ att_src,
                                const float* __restrict__ att_dst, int n) {
    int node = blockIdx.x * blockDim.x + threadIdx.x;
    if (node >= n) return;
    const __half2* xr = g_xs2h + (size_t)node * (OUT_CH / 2);
    float ss = 0.f, sd = 0.f;
    #pragma unroll
    for (int c = 0; c < OUT_CH / 2; c++) {
        float2 v = __half22float2(xr[c]);
        ss += v.x * att_src[2 * c] + v.y * att_src[2 * c + 1];
        sd += v.x * att_dst[2 * c] + v.y * att_dst[2 * c + 1];
    }
    g_asrc2[node] = ss;
    g_adst2[node] = sd;
}

// ---------------- CSR aggregation: one warp per dst node ----------------------
// Lane l owns channels [8l..8l+7] (one LDG.128 per edge). Explicit batch-load
// then compute phases keep 8 loads in flight per 4-edge group.
__global__ void agg1_csr_kernel(const float* __restrict__ bias, int n) {
    int warp = (blockIdx.x * blockDim.x + threadIdx.x) >> 5;
    int lane = threadIdx.x & 31;
    if (warp >= n) return;
    const int node = warp;
    const int start = g_rowstart[node];
    const int end   = g_rowstart[node + 1];
    const float adst = (lane < HEADS) ? g_adst1[node * HEADS + lane] : 0.f;
    const int hsel = lane >> 2;         // head owning channels [8l..8l+7]

    float4 accA = {0.f, 0.f, 0.f, 0.f};
    float4 accB = {0.f, 0.f, 0.f, 0.f};
    float den = 0.f;                    // lane h (<8) holds den for head h

    for (int base = start; base < end; base += 32) {
        int m = end - base; if (m > 32) m = 32;
        int idx = (base + lane < end) ? g_csr_src[base + lane] : 0;
        int t = 0;
        for (; t + 3 < m; t += 4) {
            int s[4]; float as[4]; uint4 u[4];
            #pragma unroll
            for (int q = 0; q < 4; q++)
                s[q] = __shfl_sync(0xffffffffu, idx, t + q);
            #pragma unroll
            for (int q = 0; q < 4; q++) {
                as[q] = (lane < HEADS) ? g_asrc1[s[q] * HEADS + lane] : 0.f;
                u[q] = ((const uint4*)(g_xs1h + (size_t)s[q] * (F1 / 2)))[lane];
            }
            #pragma unroll
            for (int q = 0; q < 4; q++) {
                float ex = (lane < HEADS) ? __expf(lrelu(as[q] + adst)) : 0.f;
                den += ex;
                float w = __shfl_sync(0xffffffffu, ex, hsel);
                float2 f0 = __half22float2(*(__half2*)&u[q].x);
                float2 f1 = __half22float2(*(__half2*)&u[q].y);
                float2 f2 = __half22float2(*(__half2*)&u[q].z);
                float2 f3 = __half22float2(*(__half2*)&u[q].w);
                accA.x += w * f0.x; accA.y += w * f0.y;
                accA.z += w * f1.x; accA.w += w * f1.y;
                accB.x += w * f2.x; accB.y += w * f2.y;
                accB.z += w * f3.x; accB.w += w * f3.y;
            }
        }
        for (; t < m; t++) {
            int s0 = __shfl_sync(0xffffffffu, idx, t);
            float as0 = (lane < HEADS) ? g_asrc1[s0 * HEADS + lane] : 0.f;
            uint4 u = ((const uint4*)(g_xs1h + (size_t)s0 * (F1 / 2)))[lane];
            float ex = (lane < HEADS) ? __expf(lrelu(as0 + adst)) : 0.f;
            den += ex;
            float w = __shfl_sync(0xffffffffu, ex, hsel);
            float2 f0 = __half22float2(*(__half2*)&u.x);
            float2 f1 = __half22float2(*(__half2*)&u.y);
            float2 f2 = __half22float2(*(__half2*)&u.z);
            float2 f3 = __half22float2(*(__half2*)&u.w);
            accA.x += w * f0.x; accA.y += w * f0.y;
            accA.z += w * f1.x; accA.w += w * f1.y;
            accB.x += w * f2.x; accB.y += w * f2.y;
            accB.z += w * f3.x; accB.w += w * f3.y;
        }
    }
    float denh = __shfl_sync(0xffffffffu, den, hsel);
    float4 bA = *(const float4*)&bias[lane * 8];
    float4 bB = *(const float4*)&bias[lane * 8 + 4];
    float4 oA, oB;
    oA.x = accA.x / denh + bA.x; oA.y = accA.y / denh + bA.y;
    oA.z = accA.z / denh + bA.z; oA.w = accA.w / denh + bA.w;
    oB.x = accB.x / denh + bB.x; oB.y = accB.y / denh + bB.y;
    oB.z = accB.z / denh + bB.z; oB.w = accB.w / denh + bB.w;
    oA.x = oA.x > 0.f ? oA.x : expm1f(oA.x);
    oA.y = oA.y > 0.f ? oA.y : expm1f(oA.y);
    oA.z = oA.z > 0.f ? oA.z : expm1f(oA.z);
    oA.w = oA.w > 0.f ? oA.w : expm1f(oA.w);
    oB.x = oB.x > 0.f ? oB.x : expm1f(oB.x);
    oB.y = oB.y > 0.f ? oB.y : expm1f(oB.y);
    oB.z = oB.z > 0.f ? oB.z : expm1f(oB.z);
    oB.w = oB.w > 0.f ? oB.w : expm1f(oB.w);
    uint4 p;
    *(__half2*)&p.x = __float22half2_rn(make_float2(oA.x, oA.y));
    *(__half2*)&p.y = __float22half2_rn(make_float2(oA.z, oA.w));
    *(__half2*)&p.z = __float22half2_rn(make_float2(oB.x, oB.y));
    *(__half2*)&p.w = __float22half2_rn(make_float2(oB.z, oB.w));
    ((uint4*)(g_hh + (size_t)node * (F1 / 2)))[lane] = p;
}

// agg2: QUARTER-warps own alternating edges (4 edges in flight / iter).
// q = lane>>3, sl = lane&7; lane covers channels [8sl..8sl+7] via one LDG.128.
// Quarters combined at the end with shfl_xor(8) + shfl_xor(16).
__global__ void agg2_csr_kernel(float* __restrict__ out,
                                const float* __restrict__ bias, int n) {
    int warp = (blockIdx.x * blockDim.x + threadIdx.x) >> 5;
    int lane = threadIdx.x & 31;
    if (warp >= n) return;
    const int node = warp;
    const int q = lane >> 3;
    const int sl = lane & 7;
    const int start = g_rowstart[node];
    const int end   = g_rowstart[node + 1];
    const float adst = g_adst2[node];

    float accA[4] = {0.f, 0.f, 0.f, 0.f};
    float accB[4] = {0.f, 0.f, 0.f, 0.f};
    float den = 0.f;
    for (int base = start; base < end; base += 32) {
        int m = end - base; if (m > 32) m = 32;
        int idx = (base + lane < end) ? g_csr_src[base + lane] : 0;
        for (int t = 0; t < m; t += 4) {
            bool ok = (t + q) < m;
            int s = __shfl_sync(0xffffffffu, idx, ok ? (t + q) : t);
            float as = g_asrc2[s];
            uint4 u = ((const uint4*)(g_xs2h + (size_t)s * (OUT_CH / 2)))[sl];
            float ex = ok ? __expf(lrelu(as + adst)) : 0.f;
            den += ex;
            float2 f0 = __half22float2(*(__half2*)&u.x);
            float2 f1 = __half22float2(*(__half2*)&u.y);
            float2 f2 = __half22float2(*(__half2*)&u.z);
            float2 f3 = __half22float2(*(__half2*)&u.w);
            accA[0] += ex * f0.x; accA[1] += ex * f0.y;
            accA[2] += ex * f1.x; accA[3] += ex * f1.y;
            accB[0] += ex * f2.x; accB[1] += ex * f2.y;
            accB[2] += ex * f3.x; accB[3] += ex * f3.y;
        }
    }
    // combine quarters (same channels, disjoint edge subsets)
    #pragma unroll
    for (int o = 8; o <= 16; o <<= 1) {
        den += __shfl_xor_sync(0xffffffffu, den, o);
        #pragma unroll
        for (int i = 0; i < 4; i++) {
            accA[i] += __shfl_xor_sync(0xffffffffu, accA[i], o);
            accB[i] += __shfl_xor_sync(0xffffffffu, accB[i], o);
        }
    }
    if (q == 0) {
        float4 bA = *(const float4*)&bias[sl * 8];
        float4 bB = *(const float4*)&bias[sl * 8 + 4];
        float4 oA, oB;
        oA.x = accA[0] / den + bA.x; oA.y = accA[1] / den + bA.y;
        oA.z = accA[2] / den + bA.z; oA.w = accA[3] / den + bA.w;
        oB.x = accB[0] / den + bB.x; oB.y = accB[1] / den + bB.y;
        oB.z = accB[2] / den + bB.z; oB.w = accB[3] / den + bB.w;
        float4* orow = (float4*)(out + (size_t)node * OUT_CH);
        orow[sl * 2]     = oA;
        orow[sl * 2 + 1] = oB;
    }
}

// ---------------- launch -----------------------------------------------------
extern "C" void kernel_launch(void* const* d_in, const int* in_sizes, int n_in,
                              void* d_out, int out_size) {
    const float* x        = (const float*)d_in[0];
    const int*   eidx     = (const int*)d_in[1];     // int32 [2, E]
    const float* W1       = (const float*)d_in[2];
    const float* att_src1 = (const float*)d_in[3];
    const float* att_dst1 = (const float*)d_in[4];
    const float* bias1    = (const float*)d_in[5];
    const float* W2       = (const float*)d_in[6];
    const float* att_src2 = (const float*)d_in[7];
    const float* att_dst2 = (const float*)d_in[8];
    const float* bias2    = (const float*)d_in[9];
    float* out = (float*)d_out;

    // GB300 ATS trap: __device__ symbols as host-side kernel args resolve to
    // the HOST shadow address (silently readable via NVLink-C2C ATS!).
    // Resolve the real device addresses explicitly.
    static __half* p_xs1h = nullptr;
    static __half* p_hh   = nullptr;
    static __half* p_xs2h = nullptr;
    static int*    p_count = nullptr;
    static cudaStream_t s1 = nullptr;
    static cudaEvent_t  e_fork = nullptr, e_join = nullptr;
    if (!p_xs1h) {
        void* p;
        cudaGetSymbolAddress(&p, g_xs1h);  p_xs1h = (__half*)p;
        cudaGetSymbolAddress(&p, g_hh);    p_hh   = (__half*)p;
        cudaGetSymbolAddress(&p, g_xs2h);  p_xs2h = (__half*)p;
        cudaGetSymbolAddress(&p, g_count); p_count = (int*)p;
        cudaStreamCreateWithFlags(&s1, cudaStreamNonBlocking);
        cudaEventCreateWithFlags(&e_fork, cudaEventDisableTiming);
        cudaEventCreateWithFlags(&e_join, cudaEventDisableTiming);
    }

    const int n = in_sizes[0] / IN_CH;     // 50000
    const int E = in_sizes[1] / 2;         // 800000
    const int* src = eidx;
    const int* dst = eidx + E;

    const int T = 256;
    const int nb = (n + 255) / 256;        // scan blocks (196)
    const int tot4 = (E + n + 4 * T - 1) / (4 * T);

    // ---- fork: CSR build on side stream, overlapped with GEMM1/att_dot1 ----
    cudaEventRecord(e_fork, (cudaStream_t)0);
    cudaStreamWaitEvent(s1, e_fork, 0);
    cudaMemsetAsync(p_count, 0, n * sizeof(int), s1);
    hist_kernel<<<tot4, T, 0, s1>>>(dst, E, n);
    scan_blk_kernel<<<nb, 256, 0, s1>>>(n);
    rows_kernel<<<nb, 256, 0, s1>>>(E, n);
    scatter_kernel<<<tot4, T, 0, s1>>>(src, dst, E, n);
    cudaEventRecord(e_join, s1);

    // ---- layer 1 (fp16 TC GEMM) on main stream ----
    {
        dim3 grid(F1 / 128, (n + 127) / 128);
        hgemm_tc<128, 128, 32, 2, 4, 4, 4, false><<<grid, 256>>>(x, W1, p_xs1h, n, F1, IN_CH);
    }
    att_dot1_kernel<<<(n * HEADS + T - 1) / T, T>>>(att_src1, att_dst1, n);

    // ---- join: aggregation needs both the CSR and the attention scores ----
    cudaStreamWaitEvent((cudaStream_t)0, e_join, 0);
    agg1_csr_kernel<<<(n * 32 + T - 1) / T, T>>>(bias1, n);

    // ---- layer 2 (fp16 TC GEMM) ----
    {
        dim3 grid(OUT_CH / 64, (n + 127) / 128);
        hgemm_tc<128, 64, 32, 4, 2, 2, 4, true><<<grid, 256>>>(p_hh, W2, p_xs2h, n, OUT_CH, F1);
    }
    att_dot2_kernel<<<(n + T - 1) / T, T>>>(att_src2, att_dst2, n);
    agg2_csr_kernel<<<(n * 32 + T - 1) / T, T>>>(out, bias2, n);
}